// round 2
// baseline (speedup 1.0000x reference)
#include <cuda_runtime.h>
#include <cuda_bf16.h>

#define N_NODES 50000
#define N_EDGES 800000
#define N_GRAPHS 64
#define FEAT 128
#define EMB 256
#define HID 512
#define VOCAB 512

// ---------------- scratch (device globals; no allocation allowed) ----------
__device__ float g_aggin1[(size_t)N_NODES * FEAT];   // 25.6 MB
__device__ float g_aggin2[(size_t)N_NODES * EMB];    // 51.2 MB
__device__ float g_h1[(size_t)N_NODES * EMB];        // 51.2 MB
__device__ float g_h2[(size_t)N_NODES * HID];        // 102.4 MB
__device__ float g_cnt[N_NODES];
__device__ float g_pooled[N_GRAPHS * HID];
__device__ float g_gcnt[N_GRAPHS];

// ---------------- zero scratch ---------------------------------------------
__global__ void k_zero() {
    const long long n1 = (long long)N_NODES * FEAT;
    const long long n2 = (long long)N_NODES * EMB;
    const long long n3 = N_NODES;
    const long long n4 = N_GRAPHS * HID;
    const long long n5 = N_GRAPHS;
    const long long total = n1 + n2 + n3 + n4 + n5;
    for (long long i = (long long)blockIdx.x * blockDim.x + threadIdx.x;
         i < total; i += (long long)gridDim.x * blockDim.x) {
        long long j = i;
        if (j < n1) { g_aggin1[j] = 0.f; continue; } j -= n1;
        if (j < n2) { g_aggin2[j] = 0.f; continue; } j -= n2;
        if (j < n3) { g_cnt[j]    = 0.f; continue; } j -= n3;
        if (j < n4) { g_pooled[j] = 0.f; continue; } j -= n4;
        g_gcnt[j] = 0.f;
    }
}

// ---------------- edge scatter: agg[dst] += feat[src] ----------------------
// one warp per edge, grid-stride. F in {128, 256}, multiple of 128.
// edge_index is int32 (JAX canonicalizes int64 -> int32 without x64 mode).
__global__ void k_scatter(const float* __restrict__ feat,
                          const int* __restrict__ ei,
                          float* __restrict__ agg,
                          float* __restrict__ cnt,   // may be null
                          int F) {
    int nwarps = (gridDim.x * blockDim.x) >> 5;
    int w = ((blockIdx.x * blockDim.x) + threadIdx.x) >> 5;
    int lane = threadIdx.x & 31;
    for (int e = w; e < N_EDGES; e += nwarps) {
        int src = ei[e];
        int dst = ei[N_EDGES + e];
        const float* fs = feat + (long long)src * F;
        float* fd = agg + (long long)dst * F;
        #pragma unroll 2
        for (int j = lane * 4; j < F; j += 128) {
            float4 v = *reinterpret_cast<const float4*>(fs + j);
            atomicAdd(fd + j + 0, v.x);
            atomicAdd(fd + j + 1, v.y);
            atomicAdd(fd + j + 2, v.z);
            atomicAdd(fd + j + 3, v.w);
        }
        if (cnt && lane == 0) atomicAdd(cnt + dst, 1.f);
    }
}

// ---------------- dual-A fused GEMM -----------------------------------------
// C[M,N] = A1[M,K1] @ B1[K1,N] + scale(A2)[M,K2] @ B2[K2,N] + bias, opt. relu
// scale(A2) row r multiplied by 1/max(cnt[r],1) when cnt != null.
#define BM 128
#define BN 64
#define BK 16
#define TM 8
#define TN 4

__global__ __launch_bounds__(256)
void k_gemm_dual(const float* __restrict__ A1, const float* __restrict__ B1, int K1,
                 const float* __restrict__ A2, const float* __restrict__ B2, int K2,
                 const float* __restrict__ cnt,
                 const float* __restrict__ bias,
                 float* __restrict__ C, int M, int N, int do_relu) {
    __shared__ __align__(16) float As[BK][BM + 4];
    __shared__ __align__(16) float Bs[BK][BN];

    int tid = threadIdx.x;
    int bm = blockIdx.x * BM;
    int bn = blockIdx.y * BN;
    int tx = tid & 15;   // 16 col groups of TN
    int ty = tid >> 4;   // 16 row groups of TM

    float acc[TM][TN];
    #pragma unroll
    for (int i = 0; i < TM; i++)
        #pragma unroll
        for (int j = 0; j < TN; j++) acc[i][j] = 0.f;

    for (int pass = 0; pass < 2; pass++) {
        const float* A = (pass == 0) ? A1 : A2;
        const float* B = (pass == 0) ? B1 : B2;
        int K = (pass == 0) ? K1 : K2;
        bool scale = (pass == 1) && (cnt != nullptr);

        for (int k0 = 0; k0 < K; k0 += BK) {
            // load A tile (BM x BK) -> As transposed: 2 float4 per thread
            #pragma unroll
            for (int i = 0; i < 2; i++) {
                int f4 = tid * 2 + i;
                int row = f4 >> 2;          // BK/4 = 4 float4 per row
                int kc  = (f4 & 3) * 4;
                int grow = bm + row;
                float4 v = make_float4(0.f, 0.f, 0.f, 0.f);
                if (grow < M) {
                    v = *reinterpret_cast<const float4*>(A + (long long)grow * K + k0 + kc);
                    if (scale) {
                        float rc = 1.f / fmaxf(cnt[grow], 1.f);
                        v.x *= rc; v.y *= rc; v.z *= rc; v.w *= rc;
                    }
                }
                As[kc + 0][row] = v.x;
                As[kc + 1][row] = v.y;
                As[kc + 2][row] = v.z;
                As[kc + 3][row] = v.w;
            }
            // load B tile (BK x BN): one float4 per thread
            {
                int brow = tid >> 4;
                int bc = (tid & 15) * 4;
                float4 v = *reinterpret_cast<const float4*>(
                    B + (long long)(k0 + brow) * N + bn + bc);
                *reinterpret_cast<float4*>(&Bs[brow][bc]) = v;
            }
            __syncthreads();

            #pragma unroll
            for (int kk = 0; kk < BK; kk++) {
                float a[TM], b[TN];
                float4 a0 = *reinterpret_cast<const float4*>(&As[kk][ty * TM]);
                float4 a1 = *reinterpret_cast<const float4*>(&As[kk][ty * TM + 4]);
                a[0]=a0.x; a[1]=a0.y; a[2]=a0.z; a[3]=a0.w;
                a[4]=a1.x; a[5]=a1.y; a[6]=a1.z; a[7]=a1.w;
                float4 b0 = *reinterpret_cast<const float4*>(&Bs[kk][tx * TN]);
                b[0]=b0.x; b[1]=b0.y; b[2]=b0.z; b[3]=b0.w;
                #pragma unroll
                for (int i = 0; i < TM; i++)
                    #pragma unroll
                    for (int j = 0; j < TN; j++)
                        acc[i][j] = fmaf(a[i], b[j], acc[i][j]);
            }
            __syncthreads();
        }
    }

    // epilogue
    int col = bn + tx * TN;
    float4 b4 = *reinterpret_cast<const float4*>(bias + col);
    #pragma unroll
    for (int i = 0; i < TM; i++) {
        int row = bm + ty * TM + i;
        if (row >= M) continue;
        float4 v;
        v.x = acc[i][0] + b4.x;
        v.y = acc[i][1] + b4.y;
        v.z = acc[i][2] + b4.z;
        v.w = acc[i][3] + b4.w;
        if (do_relu) {
            v.x = fmaxf(v.x, 0.f); v.y = fmaxf(v.y, 0.f);
            v.z = fmaxf(v.z, 0.f); v.w = fmaxf(v.w, 0.f);
        }
        *reinterpret_cast<float4*>(C + (long long)row * N + col) = v;
    }
}

// ---------------- per-graph node counts -------------------------------------
__global__ void k_gcnt(const int* __restrict__ batch) {
    for (int i = blockIdx.x * blockDim.x + threadIdx.x; i < N_NODES;
         i += gridDim.x * blockDim.x)
        atomicAdd(&g_gcnt[batch[i]], 1.f);
}

// ---------------- segment-sum pooling over sorted batch ids -----------------
#define POOL_CH 512
__global__ void k_pool(const float* __restrict__ h,
                       const int* __restrict__ batch) {
    int col = blockIdx.y * blockDim.x + threadIdx.x;       // 0..511
    long long start = (long long)blockIdx.x * POOL_CH;
    long long end = start + POOL_CH;
    if (end > N_NODES) end = N_NODES;
    if (start >= N_NODES) return;
    int cur = batch[start];
    float s = 0.f;
    for (long long i = start; i < end; i++) {
        int g = batch[i];
        if (g != cur) {
            atomicAdd(&g_pooled[cur * HID + col], s);
            s = 0.f; cur = g;
        }
        s += h[i * HID + col];
    }
    atomicAdd(&g_pooled[cur * HID + col], s);
}

// ---------------- heads: hidden = p@Wh+bh, cell = p@Wc+bc -------------------
__global__ __launch_bounds__(512)
void k_head(const float* __restrict__ Wh, const float* __restrict__ bh,
            const float* __restrict__ Wc, const float* __restrict__ bc,
            float* __restrict__ out_hidden, float* __restrict__ out_cell) {
    int g = blockIdx.x;
    int t = threadIdx.x;
    __shared__ float p[HID];
    float inv = 1.f / fmaxf(g_gcnt[g], 1.f);
    p[t] = g_pooled[g * HID + t] * inv;
    __syncthreads();
    float h = 0.f, c = 0.f;
    #pragma unroll 8
    for (int k = 0; k < HID; k++) {
        float pk = p[k];
        h = fmaf(pk, Wh[k * HID + t], h);
        c = fmaf(pk, Wc[k * HID + t], c);
    }
    out_hidden[g * HID + t] = h + bh[t];
    out_cell[g * HID + t]   = c + bc[t];
}

// ---------------- logits = log_softmax(hidden @ Wout + bout) ----------------
__global__ __launch_bounds__(512)
void k_logits(const float* __restrict__ hidden,
              const float* __restrict__ Wout, const float* __restrict__ bout,
              float* __restrict__ logits) {
    int g = blockIdx.x;
    int t = threadIdx.x;
    __shared__ float h[HID];
    __shared__ float red[VOCAB];
    h[t] = hidden[g * HID + t];
    __syncthreads();
    float z = bout[t];
    #pragma unroll 8
    for (int k = 0; k < HID; k++)
        z = fmaf(h[k], Wout[k * VOCAB + t], z);

    red[t] = z;
    __syncthreads();
    for (int s = 256; s > 0; s >>= 1) {
        if (t < s) red[t] = fmaxf(red[t], red[t + s]);
        __syncthreads();
    }
    float mx = red[0];
    __syncthreads();
    red[t] = expf(z - mx);
    __syncthreads();
    for (int s = 256; s > 0; s >>= 1) {
        if (t < s) red[t] += red[t + s];
        __syncthreads();
    }
    float lse = logf(red[0]) + mx;
    logits[g * VOCAB + t] = z - lse;
}

// ---------------- launch ----------------------------------------------------
extern "C" void kernel_launch(void* const* d_in, const int* in_sizes, int n_in,
                              void* d_out, int out_size) {
    const float* x       = (const float*)d_in[1];
    const int*   ei      = (const int*)d_in[2];
    const int*   batch   = (const int*)d_in[3];
    const float* W_root1 = (const float*)d_in[4];
    const float* W_rel1  = (const float*)d_in[5];
    const float* b1      = (const float*)d_in[6];
    const float* W_root2 = (const float*)d_in[7];
    const float* W_rel2  = (const float*)d_in[8];
    const float* b2      = (const float*)d_in[9];
    const float* Wh      = (const float*)d_in[10];
    const float* bh      = (const float*)d_in[11];
    const float* Wc      = (const float*)d_in[12];
    const float* bc      = (const float*)d_in[13];
    const float* Wout    = (const float*)d_in[14];
    const float* bout    = (const float*)d_in[15];
    float* out = (float*)d_out;

    float *p_aggin1, *p_aggin2, *p_h1, *p_h2, *p_cnt;
    cudaGetSymbolAddress((void**)&p_aggin1, g_aggin1);
    cudaGetSymbolAddress((void**)&p_aggin2, g_aggin2);
    cudaGetSymbolAddress((void**)&p_h1, g_h1);
    cudaGetSymbolAddress((void**)&p_h2, g_h2);
    cudaGetSymbolAddress((void**)&p_cnt, g_cnt);

    float* out_logits = out;
    float* out_hidden = out + N_GRAPHS * HID;
    float* out_cell   = out + 2 * N_GRAPHS * HID;

    // 1. zero scratch
    k_zero<<<4096, 256>>>();

    // 2. scatter raw x into aggin1 (+ in-degree counts)
    k_scatter<<<2048, 256>>>(x, ei, p_aggin1, p_cnt, FEAT);

    // 3. h1 = relu(x@W_root1 + (aggin1/cnt)@W_rel1 + b1)
    {
        dim3 grid((N_NODES + BM - 1) / BM, EMB / BN);
        k_gemm_dual<<<grid, 256>>>(x, W_root1, FEAT,
                                   p_aggin1, W_rel1, FEAT,
                                   p_cnt, b1, p_h1, N_NODES, EMB, 1);
    }

    // 4. scatter h1 into aggin2
    k_scatter<<<2048, 256>>>(p_h1, ei, p_aggin2, nullptr, EMB);

    // 5. h2 = relu(h1@W_root2 + (aggin2/cnt)@W_rel2 + b2)
    {
        dim3 grid((N_NODES + BM - 1) / BM, HID / BN);
        k_gemm_dual<<<grid, 256>>>(p_h1, W_root2, EMB,
                                   p_aggin2, W_rel2, EMB,
                                   p_cnt, b2, p_h2, N_NODES, HID, 1);
    }

    // 6. per-graph counts + pooled sum
    k_gcnt<<<256, 256>>>(batch);
    {
        dim3 grid((N_NODES + POOL_CH - 1) / POOL_CH, HID / 128);
        k_pool<<<grid, 128>>>(p_h2, batch);
    }

    // 7. heads
    k_head<<<N_GRAPHS, HID>>>(Wh, bh, Wc, bc, out_hidden, out_cell);

    // 8. logits = log_softmax(hidden @ Wout + bout)
    k_logits<<<N_GRAPHS, VOCAB>>>(out_hidden, Wout, bout, out_logits);
}

// round 3
// speedup vs baseline: 1.3591x; 1.3591x over previous
#include <cuda_runtime.h>
#include <cuda_bf16.h>

#define N_NODES 50000
#define N_EDGES 800000
#define N_GRAPHS 64
#define FEAT 128
#define EMB 256
#define HID 512
#define VOCAB 512

// ---------------- scratch (device globals; no allocation allowed) ----------
__device__ float g_aggin1[(size_t)N_NODES * FEAT];   // 25.6 MB (fully overwritten)
__device__ float g_aggin2[(size_t)N_NODES * EMB];    // 51.2 MB (fully overwritten)
__device__ float g_h1[(size_t)N_NODES * EMB];        // 51.2 MB
__device__ float g_h2[(size_t)N_NODES * HID];        // 102.4 MB
__device__ int   g_deg[N_NODES];
__device__ int   g_rowstart[N_NODES];
__device__ int   g_cursor[N_NODES];
__device__ int   g_srcs[N_EDGES];
__device__ float g_pooled[N_GRAPHS * HID];
__device__ float g_gcnt[N_GRAPHS];

// ---------------- zero the small scratch ------------------------------------
__global__ void k_zero() {
    int i = blockIdx.x * blockDim.x + threadIdx.x;
    int stride = gridDim.x * blockDim.x;
    for (int j = i; j < N_NODES; j += stride) g_deg[j] = 0;
    for (int j = i; j < N_GRAPHS * HID; j += stride) g_pooled[j] = 0.f;
    for (int j = i; j < N_GRAPHS; j += stride) g_gcnt[j] = 0.f;
}

// ---------------- in-degree histogram ---------------------------------------
__global__ void k_hist(const int* __restrict__ ei) {
    int i = blockIdx.x * blockDim.x + threadIdx.x;
    int stride = gridDim.x * blockDim.x;
    for (int e = i; e < N_EDGES; e += stride)
        atomicAdd(&g_deg[ei[N_EDGES + e]], 1);
}

// ---------------- exclusive scan of degrees (1 block, 1024 threads) ---------
__global__ __launch_bounds__(1024)
void k_scan() {
    __shared__ int sums[1024];
    int t = threadIdx.x;
    const int CH = (N_NODES + 1023) / 1024;   // 49
    int base = t * CH;
    int local = 0;
    #pragma unroll 4
    for (int i = 0; i < CH; i++) {
        int idx = base + i;
        if (idx < N_NODES) local += g_deg[idx];
    }
    sums[t] = local;
    __syncthreads();
    // Hillis-Steele inclusive scan
    for (int off = 1; off < 1024; off <<= 1) {
        int v = (t >= off) ? sums[t - off] : 0;
        __syncthreads();
        sums[t] += v;
        __syncthreads();
    }
    int offset = (t == 0) ? 0 : sums[t - 1];
    for (int i = 0; i < CH; i++) {
        int idx = base + i;
        if (idx < N_NODES) {
            g_rowstart[idx] = offset;
            g_cursor[idx] = offset;
            offset += g_deg[idx];
        }
    }
}

// ---------------- fill sorted src list by dst bin ----------------------------
__global__ void k_fill(const int* __restrict__ ei) {
    int i = blockIdx.x * blockDim.x + threadIdx.x;
    int stride = gridDim.x * blockDim.x;
    for (int e = i; e < N_EDGES; e += stride) {
        int src = ei[e];
        int dst = ei[N_EDGES + e];
        int pos = atomicAdd(&g_cursor[dst], 1);
        g_srcs[pos] = src;
    }
}

// ---------------- gather: agg[v] = mean over in-edges of feat[src] ----------
// one block per dst node, blockDim.x = F (128 or 256)
__global__ void k_gather(const float* __restrict__ feat,
                         float* __restrict__ agg, int F) {
    int v = blockIdx.x;
    int t = threadIdx.x;
    int start = g_rowstart[v];
    int d = g_deg[v];
    float s0 = 0.f, s1 = 0.f, s2 = 0.f, s3 = 0.f;
    int i = 0;
    for (; i + 4 <= d; i += 4) {
        int e0 = g_srcs[start + i + 0];
        int e1 = g_srcs[start + i + 1];
        int e2 = g_srcs[start + i + 2];
        int e3 = g_srcs[start + i + 3];
        s0 += feat[(long long)e0 * F + t];
        s1 += feat[(long long)e1 * F + t];
        s2 += feat[(long long)e2 * F + t];
        s3 += feat[(long long)e3 * F + t];
    }
    for (; i < d; i++)
        s0 += feat[(long long)g_srcs[start + i] * F + t];
    float inv = 1.f / fmaxf((float)d, 1.f);
    agg[(long long)v * F + t] = (s0 + s1 + s2 + s3) * inv;
}

// ---------------- dual-A fused GEMM -----------------------------------------
// C[M,N] = A1[M,K1] @ B1[K1,N] + A2[M,K2] @ B2[K2,N] + bias, opt. relu
#define BM 128
#define BN 64
#define BK 16
#define TM 8
#define TN 4

__global__ __launch_bounds__(256)
void k_gemm_dual(const float* __restrict__ A1, const float* __restrict__ B1, int K1,
                 const float* __restrict__ A2, const float* __restrict__ B2, int K2,
                 const float* __restrict__ bias,
                 float* __restrict__ C, int M, int N, int do_relu) {
    __shared__ __align__(16) float As[BK][BM + 4];
    __shared__ __align__(16) float Bs[BK][BN];

    int tid = threadIdx.x;
    int bm = blockIdx.x * BM;
    int bn = blockIdx.y * BN;
    int tx = tid & 15;
    int ty = tid >> 4;

    float acc[TM][TN];
    #pragma unroll
    for (int i = 0; i < TM; i++)
        #pragma unroll
        for (int j = 0; j < TN; j++) acc[i][j] = 0.f;

    for (int pass = 0; pass < 2; pass++) {
        const float* A = (pass == 0) ? A1 : A2;
        const float* B = (pass == 0) ? B1 : B2;
        int K = (pass == 0) ? K1 : K2;

        for (int k0 = 0; k0 < K; k0 += BK) {
            #pragma unroll
            for (int i = 0; i < 2; i++) {
                int f4 = tid * 2 + i;
                int row = f4 >> 2;
                int kc  = (f4 & 3) * 4;
                int grow = bm + row;
                float4 v = make_float4(0.f, 0.f, 0.f, 0.f);
                if (grow < M)
                    v = *reinterpret_cast<const float4*>(A + (long long)grow * K + k0 + kc);
                As[kc + 0][row] = v.x;
                As[kc + 1][row] = v.y;
                As[kc + 2][row] = v.z;
                As[kc + 3][row] = v.w;
            }
            {
                int brow = tid >> 4;
                int bc = (tid & 15) * 4;
                float4 v = *reinterpret_cast<const float4*>(
                    B + (long long)(k0 + brow) * N + bn + bc);
                *reinterpret_cast<float4*>(&Bs[brow][bc]) = v;
            }
            __syncthreads();

            #pragma unroll
            for (int kk = 0; kk < BK; kk++) {
                float a[TM], b[TN];
                float4 a0 = *reinterpret_cast<const float4*>(&As[kk][ty * TM]);
                float4 a1 = *reinterpret_cast<const float4*>(&As[kk][ty * TM + 4]);
                a[0]=a0.x; a[1]=a0.y; a[2]=a0.z; a[3]=a0.w;
                a[4]=a1.x; a[5]=a1.y; a[6]=a1.z; a[7]=a1.w;
                float4 b0 = *reinterpret_cast<const float4*>(&Bs[kk][tx * TN]);
                b[0]=b0.x; b[1]=b0.y; b[2]=b0.z; b[3]=b0.w;
                #pragma unroll
                for (int i = 0; i < TM; i++)
                    #pragma unroll
                    for (int j = 0; j < TN; j++)
                        acc[i][j] = fmaf(a[i], b[j], acc[i][j]);
            }
            __syncthreads();
        }
    }

    int col = bn + tx * TN;
    float4 b4 = *reinterpret_cast<const float4*>(bias + col);
    #pragma unroll
    for (int i = 0; i < TM; i++) {
        int row = bm + ty * TM + i;
        if (row >= M) continue;
        float4 v;
        v.x = acc[i][0] + b4.x;
        v.y = acc[i][1] + b4.y;
        v.z = acc[i][2] + b4.z;
        v.w = acc[i][3] + b4.w;
        if (do_relu) {
            v.x = fmaxf(v.x, 0.f); v.y = fmaxf(v.y, 0.f);
            v.z = fmaxf(v.z, 0.f); v.w = fmaxf(v.w, 0.f);
        }
        *reinterpret_cast<float4*>(C + (long long)row * N + col) = v;
    }
}

// ---------------- per-graph node counts -------------------------------------
__global__ void k_gcnt(const int* __restrict__ batch) {
    for (int i = blockIdx.x * blockDim.x + threadIdx.x; i < N_NODES;
         i += gridDim.x * blockDim.x)
        atomicAdd(&g_gcnt[batch[i]], 1.f);
}

// ---------------- segment-sum pooling over sorted batch ids -----------------
#define POOL_CH 512
__global__ void k_pool(const float* __restrict__ h,
                       const int* __restrict__ batch) {
    int col = blockIdx.y * blockDim.x + threadIdx.x;
    long long start = (long long)blockIdx.x * POOL_CH;
    long long end = start + POOL_CH;
    if (end > N_NODES) end = N_NODES;
    if (start >= N_NODES) return;
    int cur = batch[start];
    float s = 0.f;
    for (long long i = start; i < end; i++) {
        int g = batch[i];
        if (g != cur) {
            atomicAdd(&g_pooled[cur * HID + col], s);
            s = 0.f; cur = g;
        }
        s += h[i * HID + col];
    }
    atomicAdd(&g_pooled[cur * HID + col], s);
}

// ---------------- heads: hidden = p@Wh+bh, cell = p@Wc+bc -------------------
__global__ __launch_bounds__(512)
void k_head(const float* __restrict__ Wh, const float* __restrict__ bh,
            const float* __restrict__ Wc, const float* __restrict__ bc,
            float* __restrict__ out_hidden, float* __restrict__ out_cell) {
    int g = blockIdx.x;
    int t = threadIdx.x;
    __shared__ float p[HID];
    float inv = 1.f / fmaxf(g_gcnt[g], 1.f);
    p[t] = g_pooled[g * HID + t] * inv;
    __syncthreads();
    float h = 0.f, c = 0.f;
    #pragma unroll 8
    for (int k = 0; k < HID; k++) {
        float pk = p[k];
        h = fmaf(pk, Wh[k * HID + t], h);
        c = fmaf(pk, Wc[k * HID + t], c);
    }
    out_hidden[g * HID + t] = h + bh[t];
    out_cell[g * HID + t]   = c + bc[t];
}

// ---------------- logits = log_softmax(hidden @ Wout + bout) ----------------
__global__ __launch_bounds__(512)
void k_logits(const float* __restrict__ hidden,
              const float* __restrict__ Wout, const float* __restrict__ bout,
              float* __restrict__ logits) {
    int g = blockIdx.x;
    int t = threadIdx.x;
    __shared__ float h[HID];
    __shared__ float red[VOCAB];
    h[t] = hidden[g * HID + t];
    __syncthreads();
    float z = bout[t];
    #pragma unroll 8
    for (int k = 0; k < HID; k++)
        z = fmaf(h[k], Wout[k * VOCAB + t], z);

    red[t] = z;
    __syncthreads();
    for (int s = 256; s > 0; s >>= 1) {
        if (t < s) red[t] = fmaxf(red[t], red[t + s]);
        __syncthreads();
    }
    float mx = red[0];
    __syncthreads();
    red[t] = expf(z - mx);
    __syncthreads();
    for (int s = 256; s > 0; s >>= 1) {
        if (t < s) red[t] += red[t + s];
        __syncthreads();
    }
    float lse = logf(red[0]) + mx;
    logits[g * VOCAB + t] = z - lse;
}

// ---------------- launch ----------------------------------------------------
extern "C" void kernel_launch(void* const* d_in, const int* in_sizes, int n_in,
                              void* d_out, int out_size) {
    const float* x       = (const float*)d_in[1];
    const int*   ei      = (const int*)d_in[2];
    const int*   batch   = (const int*)d_in[3];
    const float* W_root1 = (const float*)d_in[4];
    const float* W_rel1  = (const float*)d_in[5];
    const float* b1      = (const float*)d_in[6];
    const float* W_root2 = (const float*)d_in[7];
    const float* W_rel2  = (const float*)d_in[8];
    const float* b2      = (const float*)d_in[9];
    const float* Wh      = (const float*)d_in[10];
    const float* bh      = (const float*)d_in[11];
    const float* Wc      = (const float*)d_in[12];
    const float* bc      = (const float*)d_in[13];
    const float* Wout    = (const float*)d_in[14];
    const float* bout    = (const float*)d_in[15];
    float* out = (float*)d_out;

    float *p_aggin1, *p_aggin2, *p_h1, *p_h2;
    cudaGetSymbolAddress((void**)&p_aggin1, g_aggin1);
    cudaGetSymbolAddress((void**)&p_aggin2, g_aggin2);
    cudaGetSymbolAddress((void**)&p_h1, g_h1);
    cudaGetSymbolAddress((void**)&p_h2, g_h2);

    float* out_logits = out;
    float* out_hidden = out + N_GRAPHS * HID;
    float* out_cell   = out + 2 * N_GRAPHS * HID;

    // 1. zero small scratch + build CSR (deg, rowstart, sorted srcs)
    k_zero<<<256, 256>>>();
    k_hist<<<1024, 256>>>(ei);
    k_scan<<<1, 1024>>>();
    k_fill<<<1024, 256>>>(ei);

    // 2. gather mean of raw x into aggin1
    k_gather<<<N_NODES, FEAT>>>(x, p_aggin1, FEAT);

    // 3. h1 = relu(x@W_root1 + aggin1@W_rel1 + b1)
    {
        dim3 grid((N_NODES + BM - 1) / BM, EMB / BN);
        k_gemm_dual<<<grid, 256>>>(x, W_root1, FEAT,
                                   p_aggin1, W_rel1, FEAT,
                                   b1, p_h1, N_NODES, EMB, 1);
    }

    // 4. gather mean of h1 into aggin2
    k_gather<<<N_NODES, EMB>>>(p_h1, p_aggin2, EMB);

    // 5. h2 = relu(h1@W_root2 + aggin2@W_rel2 + b2)
    {
        dim3 grid((N_NODES + BM - 1) / BM, HID / BN);
        k_gemm_dual<<<grid, 256>>>(p_h1, W_root2, EMB,
                                   p_aggin2, W_rel2, EMB,
                                   b2, p_h2, N_NODES, HID, 1);
    }

    // 6. per-graph counts + pooled sum
    k_gcnt<<<256, 256>>>(batch);
    {
        dim3 grid((N_NODES + POOL_CH - 1) / POOL_CH, HID / 128);
        k_pool<<<grid, 128>>>(p_h2, batch);
    }

    // 7. heads
    k_head<<<N_GRAPHS, HID>>>(Wh, bh, Wc, bc, out_hidden, out_cell);

    // 8. logits
    k_logits<<<N_GRAPHS, VOCAB>>>(out_hidden, Wout, bout, out_logits);
}